// round 13
// baseline (speedup 1.0000x reference)
#include <cuda_runtime.h>
#include <cuda_fp16.h>
#include <stdint.h>

// ============================================================================
// LinkPrediction on GB300 (sm_103 base-target safe: mma.sync + ldmatrix;
// tcgen05 unusable: harness PTX targets sm_103 without 'a').
//
//   out[e] = relu( relu(x[src])@W1top + relu(x[dst])@W1bot + b1 ) @ W2 + b2
//
//   K0: pre-swizzle Wcat^T = [1024 n][128 k] fp16 image (ldmatrix-ready).
//   Kd: detect whether the harness delivered edges as int64 or int32.
//   K1: AB[node,1024] = relu(x_node) @ Wcat via HMMA m16n8k16 (at the legacy
//       HMMA roofline ~244 TF/s; left alone).
//   K2: cp.async 3-stage pipelined gather (32 edges/stage, 64KB/stage) +
//       smem-fed epilogue. In-flight data lives in smem, not registers ->
//       DRAM saturation decoupled from occupancy.
// ============================================================================

#define TILE_M   128
#define HID      128

__device__ __align__(16) __half g_Wsw[1024 * 128];           // swizzled Wcat^T (256 KB)
__device__ __align__(16) __half g_AB[(size_t)100096 * 1024]; // per-node fp16 (~205 MB)
__device__ int g_e64;                                        // 1 = int64 edges, 0 = int32

__device__ __forceinline__ uint32_t smem_u32(const void* p) {
    uint32_t a;
    asm("{ .reg .u64 t; cvta.to.shared.u64 t, %1; cvt.u32.u64 %0, t; }" : "=r"(a) : "l"(p));
    return a;
}

__device__ __host__ __forceinline__ uint32_t swiz16(uint32_t row, uint32_t c) {
    return ((c & ~7u) | ((c ^ row) & 7u)) << 4;
}

__device__ __forceinline__ void ldm_x4(uint32_t* r, uint32_t addr) {
    asm volatile("ldmatrix.sync.aligned.m8n8.x4.shared.b16 {%0,%1,%2,%3}, [%4];"
                 : "=r"(r[0]), "=r"(r[1]), "=r"(r[2]), "=r"(r[3]) : "r"(addr));
}

__device__ __forceinline__ void mma16816(float* d, const uint32_t* a,
                                         uint32_t b0, uint32_t b1) {
    asm volatile(
        "mma.sync.aligned.m16n8k16.row.col.f32.f16.f16.f32 "
        "{%0,%1,%2,%3}, {%4,%5,%6,%7}, {%8,%9}, {%0,%1,%2,%3};"
        : "+f"(d[0]), "+f"(d[1]), "+f"(d[2]), "+f"(d[3])
        : "r"(a[0]), "r"(a[1]), "r"(a[2]), "r"(a[3]), "r"(b0), "r"(b1));
}

__device__ __forceinline__ void cp_async16(uint32_t dst, const void* src) {
    asm volatile("cp.async.cg.shared.global [%0], [%1], 16;" :: "r"(dst), "l"(src));
}

#define LDS128(v, addr) \
    asm volatile("ld.shared.v4.b32 {%0,%1,%2,%3}, [%4];" \
                 : "=r"((v).x), "=r"((v).y), "=r"((v).z), "=r"((v).w) : "r"(addr))

// ============================================================================
// Kd: edge-dtype oracle. int64 edges (<100000) => every odd int32 word is 0.
// ============================================================================
__global__ void kd_detect(const int* __restrict__ E32, int n_words) {
    __shared__ int any_nz;
    if (threadIdx.x == 0) any_nz = 0;
    __syncthreads();
    int stride = (n_words / 2) / 256;
    if (stride < 1) stride = 1;
    int nz = 0;
    for (int i = threadIdx.x; i < 256; i += blockDim.x) {
        int idx = 2 * (i * stride) + 1;
        if (idx < n_words && E32[idx] != 0) nz = 1;
    }
    if (nz) atomicOr(&any_nz, 1);
    __syncthreads();
    if (threadIdx.x == 0) g_e64 = any_nz ? 0 : 1;
}

// ============================================================================
// K0: g_Wsw[n][k] = Wcat[k][n] (fp16), swizzled.
// ============================================================================
__global__ void k0_prepw(const float* __restrict__ W1) {
    int idx = blockIdx.x * blockDim.x + threadIdx.x;
    if (idx >= 1024 * 128) return;
    int n = idx >> 7;
    int k = idx & 127;
    float val = (n < 512) ? W1[k * 512 + n] : W1[(k + 128) * 512 + (n - 512)];
    uint32_t c = (uint32_t)(k >> 3), i = (uint32_t)(k & 7);
    g_Wsw[(size_t)n * 128 + (swiz16((uint32_t)n, c) >> 1) + i] = __float2half(val);
}

// ============================================================================
// K1: 256 thr = 8 warps (4M x 2N), warp tile 32x64, 8 N-chunks of 128.
// cp.async double-buffered B; staged coalesced fp16 writeback. At HMMA floor.
// ============================================================================
__global__ void __launch_bounds__(256, 2) k1_gemm(const float* __restrict__ X, int n_nodes) {
    extern __shared__ char smem[];
    uint32_t smemA = smem_u32(smem);
    uint32_t smemB[2] = { smemA + 32768u, smemA + 65536u };

    int tid = threadIdx.x, wid = tid >> 5, lid = tid & 31;
    int warp_m = wid & 3;
    int warp_n = wid >> 2;

    {
        const int4* src = (const int4*)(g_Wsw);
#pragma unroll
        for (int i = tid; i < 2048; i += 256) cp_async16(smemB[0] + i * 16, src + i);
        asm volatile("cp.async.commit_group;");
    }

    {
        int row = tid >> 1;
        int kbase = (tid & 1) * 64;
        int node = blockIdx.x * TILE_M + row;
        bool v = (node < n_nodes);
        const float4* xr = (const float4*)(X + (size_t)(v ? node : 0) * HID + kbase);
#pragma unroll
        for (int j = 0; j < 16; j++) {
            float4 val = v ? __ldg(xr + j) : make_float4(0.f, 0.f, 0.f, 0.f);
            val.x = fmaxf(val.x, 0.f); val.y = fmaxf(val.y, 0.f);
            val.z = fmaxf(val.z, 0.f); val.w = fmaxf(val.w, 0.f);
            union { __half2 h; uint32_t u; } p0, p1;
            p0.h = __floats2half2_rn(val.x, val.y);
            p1.h = __floats2half2_rn(val.z, val.w);
            int col = kbase + j * 4;
            uint32_t c = (uint32_t)(col >> 3), i = (uint32_t)(col & 7);
            uint32_t dst = smemA + (uint32_t)row * 256u + swiz16((uint32_t)row, c) + i * 2u;
            asm volatile("st.shared.v2.b32 [%0], {%1, %2};" :: "r"(dst), "r"(p0.u), "r"(p1.u));
        }
    }

    size_t ctabase = (size_t)blockIdx.x * TILE_M;

    uint32_t rowA_base = (uint32_t)(warp_m * 32) + (uint32_t)(lid & 15);
    uint32_t cA_lane = (uint32_t)(lid >> 4);
    uint32_t rowB_base = (uint32_t)(warp_n * 64) + (uint32_t)(((lid >> 4) << 3) + (lid & 7));
    uint32_t cB_lane = (uint32_t)((lid >> 3) & 1);

    for (int chunk = 0; chunk < 8; chunk++) {
        int cur = chunk & 1;
        __syncthreads();
        if (chunk + 1 < 8) {
            const int4* src = (const int4*)(g_Wsw + (size_t)(chunk + 1) * 16384);
            uint32_t dstb = smemB[cur ^ 1];
#pragma unroll
            for (int i = tid; i < 2048; i += 256) cp_async16(dstb + i * 16, src + i);
            asm volatile("cp.async.commit_group;");
            asm volatile("cp.async.wait_group 1;");
        } else {
            asm volatile("cp.async.wait_group 0;");
        }
        __syncthreads();

        float acc[2][8][4];
#pragma unroll
        for (int mt = 0; mt < 2; mt++)
#pragma unroll
            for (int nt = 0; nt < 8; nt++)
#pragma unroll
                for (int q = 0; q < 4; q++) acc[mt][nt][q] = 0.f;

        uint32_t sB = smemB[cur];
#pragma unroll
        for (int ks = 0; ks < 8; ks++) {
            uint32_t a[2][4];
#pragma unroll
            for (int mt = 0; mt < 2; mt++) {
                uint32_t row = rowA_base + (uint32_t)(mt * 16);
                uint32_t c = (uint32_t)(ks * 2) + cA_lane;
                ldm_x4(a[mt], smemA + row * 256u + swiz16(row, c));
            }
#pragma unroll
            for (int ntp = 0; ntp < 4; ntp++) {
                uint32_t bb[4];
                uint32_t row = rowB_base + (uint32_t)(ntp * 16);
                uint32_t c = (uint32_t)(ks * 2) + cB_lane;
                ldm_x4(bb, sB + row * 256u + swiz16(row, c));
                mma16816(acc[0][2 * ntp],     a[0], bb[0], bb[1]);
                mma16816(acc[0][2 * ntp + 1], a[0], bb[2], bb[3]);
                mma16816(acc[1][2 * ntp],     a[1], bb[0], bb[1]);
                mma16816(acc[1][2 * ntp + 1], a[1], bb[2], bb[3]);
            }
        }
        __syncthreads();

        {
            uint32_t r0 = (uint32_t)(lid >> 2);
            uint32_t inner = (uint32_t)(lid & 3) * 4u;
#pragma unroll
            for (int mt = 0; mt < 2; mt++) {
#pragma unroll
                for (int nt = 0; nt < 8; nt++) {
                    uint32_t c16 = (uint32_t)(warp_n * 8 + nt);
                    uint32_t rowa = (uint32_t)(warp_m * 32 + mt * 16) + r0;
                    uint32_t rowb = rowa + 8;
                    union { __half2 h; uint32_t u; } h01, h23;
                    h01.h = __floats2half2_rn(acc[mt][nt][0], acc[mt][nt][1]);
                    h23.h = __floats2half2_rn(acc[mt][nt][2], acc[mt][nt][3]);
                    asm volatile("st.shared.b32 [%0], %1;"
                                 :: "r"(sB + rowa * 256u + swiz16(rowa, c16) + inner), "r"(h01.u));
                    asm volatile("st.shared.b32 [%0], %1;"
                                 :: "r"(sB + rowb * 256u + swiz16(rowb, c16) + inner), "r"(h23.u));
                }
            }
        }
        __syncthreads();

        {
            const char* stp = smem + 32768 + cur * 32768;
#pragma unroll
            for (int i = tid; i < 2048; i += 256) {
                uint32_t row = (uint32_t)(i >> 4), c16 = (uint32_t)(i & 15);
                int4 v = *(const int4*)(stp + row * 256u + swiz16(row, c16));
                *(int4*)(g_AB + (ctabase + row) * 1024 + chunk * 128 + c16 * 8) = v;
            }
        }
    }
}

// ============================================================================
// K2: cp.async pipelined edge gather. 512 thr, 1 CTA/SM, 3 x 64KB stages.
// Stage = 32 edges: rows 0..31 = src halves (cols 0..511), 32..63 = dst halves
// (cols 512..1023); each row 1KB, 16B chunks interleaved (even->first 512B,
// odd->second 512B) so lane-l LDS.128 at l*16 / 512+l*16 is conflict-free.
// Compute: warp w owns edges 2w, 2w+1 of the stage; half2 bias+relu, fp32 fma.
// ============================================================================
__global__ void __launch_bounds__(512, 1) k2_pipe(const void* __restrict__ Ev,
                                                  const float* __restrict__ b1,
                                                  const float* __restrict__ W2,
                                                  const float* __restrict__ b2,
                                                  float* __restrict__ out,
                                                  int n_edges, int n_nodes, int epc) {
    extern __shared__ char sm2[];
    uint32_t sb0 = smem_u32(sm2);
    int tid = threadIdx.x, lid = tid & 31, w = tid >> 5;
    const long long* Ea = (const long long*)Ev;
    const int*       Eb = (const int*)Ev;
    int e64 = g_e64;

    int estart = blockIdx.x * epc;
    int ecount = min(epc, n_edges - estart);
    if (ecount <= 0) return;
    int nst = (ecount + 31) >> 5;
    int eend = estart + ecount;

    // per-lane constants: lane owns cols cb..cb+15
    int cb = lid * 16;
    __half2 b1h[8];
    float w2a[16], w2b[16];
#pragma unroll
    for (int j = 0; j < 8; j++)
        b1h[j] = __floats2half2_rn(__ldg(b1 + cb + 2 * j), __ldg(b1 + cb + 2 * j + 1));
#pragma unroll
    for (int j = 0; j < 16; j++) {
        w2a[j] = __ldg(W2 + (cb + j) * 2);
        w2b[j] = __ldg(W2 + (cb + j) * 2 + 1);
    }
    float b20 = __ldg(b2), b21 = __ldg(b2 + 1);

    // ---- stage issue: 4096 16B chunks, 8 per thread ----
    int rowgrp = tid >> 6;        // 0..7
    int cch = tid & 63;           // chunk within 1KB row
    uint32_t soff = (uint32_t)(((cch & 1) << 9) | ((cch >> 1) << 4));
    auto issue_stage = [&](int s) {
        uint32_t sb = sb0 + (uint32_t)(s % 3) * 65536u;
        int stgbase = estart + s * 32;
#pragma unroll
        for (int i = 0; i < 8; i++) {
            int row = rowgrp + i * 8;           // 0..63
            int side = row >> 5;                // 0=src, 1=dst
            int e = min(stgbase + (row & 31), n_edges - 1);
            int idx = e64 ? (int)__ldg(Ea + (size_t)side * n_edges + e)
                          : __ldg(Eb + (size_t)side * n_edges + e);
            idx = min(max(idx, 0), n_nodes - 1);
            const char* gsrc = (const char*)g_AB + (size_t)idx * 2048
                             + (size_t)side * 1024 + (size_t)cch * 16;
            cp_async16(sb + (uint32_t)row * 1024u + soff, gsrc);
        }
        asm volatile("cp.async.commit_group;");
    };

    issue_stage(0);
    if (nst > 1) issue_stage(1);

    for (int s = 0; s < nst; s++) {
        if (s + 1 < nst) asm volatile("cp.async.wait_group 1;");
        else             asm volatile("cp.async.wait_group 0;");
        __syncthreads();

        uint32_t sb = sb0 + (uint32_t)(s % 3) * 65536u;
        int e0 = estart + s * 32 + 2 * w;

        uint32_t ps = sb + (uint32_t)(2 * w) * 1024u + (uint32_t)lid * 16u;
        uint32_t pd = sb + (uint32_t)(32 + 2 * w) * 1024u + (uint32_t)lid * 16u;
        int4 A00, A01, V00, V01, A10, A11, V10, V11;
        LDS128(A00, ps);          LDS128(A01, ps + 512u);
        LDS128(V00, pd);          LDS128(V01, pd + 512u);
        LDS128(A10, ps + 1024u);  LDS128(A11, ps + 1536u);
        LDS128(V10, pd + 1024u);  LDS128(V11, pd + 1536u);

        const __half2 z2 = __float2half2_rn(0.f);
        float x0 = 0.f, x1 = 0.f, y0 = 0.f, y1 = 0.f;
#pragma unroll
        for (int q = 0; q < 4; q++) {
            __half2 ha = ((const __half2*)&A00)[q];
            __half2 hv = ((const __half2*)&V00)[q];
            __half2 h = __hmax2(__hadd2(__hadd2(ha, hv), b1h[q]), z2);
            float2 f = __half22float2(h);
            x0 = fmaf(f.x, w2a[2 * q], x0);     x1 = fmaf(f.x, w2b[2 * q], x1);
            x0 = fmaf(f.y, w2a[2 * q + 1], x0); x1 = fmaf(f.y, w2b[2 * q + 1], x1);

            __half2 ga = ((const __half2*)&A10)[q];
            __half2 gv = ((const __half2*)&V10)[q];
            __half2 g = __hmax2(__hadd2(__hadd2(ga, gv), b1h[q]), z2);
            float2 fg = __half22float2(g);
            y0 = fmaf(fg.x, w2a[2 * q], y0);     y1 = fmaf(fg.x, w2b[2 * q], y1);
            y0 = fmaf(fg.y, w2a[2 * q + 1], y0); y1 = fmaf(fg.y, w2b[2 * q + 1], y1);
        }
#pragma unroll
        for (int q = 0; q < 4; q++) {
            __half2 ha = ((const __half2*)&A01)[q];
            __half2 hv = ((const __half2*)&V01)[q];
            __half2 h = __hmax2(__hadd2(__hadd2(ha, hv), b1h[4 + q]), z2);
            float2 f = __half22float2(h);
            x0 = fmaf(f.x, w2a[8 + 2 * q], x0);     x1 = fmaf(f.x, w2b[8 + 2 * q], x1);
            x0 = fmaf(f.y, w2a[8 + 2 * q + 1], x0); x1 = fmaf(f.y, w2b[8 + 2 * q + 1], x1);

            __half2 ga = ((const __half2*)&A11)[q];
            __half2 gv = ((const __half2*)&V11)[q];
            __half2 g = __hmax2(__hadd2(__hadd2(ga, gv), b1h[4 + q]), z2);
            float2 fg = __half22float2(g);
            y0 = fmaf(fg.x, w2a[8 + 2 * q], y0);     y1 = fmaf(fg.x, w2b[8 + 2 * q], y1);
            y0 = fmaf(fg.y, w2a[8 + 2 * q + 1], y0); y1 = fmaf(fg.y, w2b[8 + 2 * q + 1], y1);
        }

#pragma unroll
        for (int sh = 16; sh >= 1; sh >>= 1) {
            x0 += __shfl_xor_sync(0xffffffffu, x0, sh);
            x1 += __shfl_xor_sync(0xffffffffu, x1, sh);
            y0 += __shfl_xor_sync(0xffffffffu, y0, sh);
            y1 += __shfl_xor_sync(0xffffffffu, y1, sh);
        }
        if (lid == 0 && e0 < eend) {
            if (e0 + 1 < eend) {
                *(float4*)(out + 2 * (size_t)e0) =
                    make_float4(x0 + b20, x1 + b21, y0 + b20, y1 + b21);
            } else {
                *(float2*)(out + 2 * (size_t)e0) = make_float2(x0 + b20, x1 + b21);
            }
        }
        __syncthreads();
        if (s + 2 < nst) issue_stage(s + 2);
    }
}

// ============================================================================
extern "C" void kernel_launch(void* const* d_in, const int* in_sizes, int n_in,
                              void* d_out, int out_size) {
    const float* X = nullptr; const void* E = nullptr;
    const float *W1 = nullptr, *b1 = nullptr, *W2 = nullptr, *b2 = nullptr;
    int n_nodes = 0, n_edges = 0;
    for (int i = 0; i < n_in; i++) {
        switch (in_sizes[i]) {
            case 12800000: X  = (const float*)d_in[i]; n_nodes = in_sizes[i] / 128; break;
            case 1000000:  E  = d_in[i];               n_edges = in_sizes[i] / 2;   break;
            case 131072:   W1 = (const float*)d_in[i]; break;
            case 512:      b1 = (const float*)d_in[i]; break;
            case 1024:     W2 = (const float*)d_in[i]; break;
            case 2:        b2 = (const float*)d_in[i]; break;
        }
    }
    if (!X || !E || !W1 || !b1 || !W2 || !b2) return;

    const int K1_SMEM = 98304;    // A 32KB + B0 32KB + B1 32KB
    const int K2_SMEM = 196608;   // 3 x 64KB stages
    cudaFuncSetAttribute(k1_gemm, cudaFuncAttributeMaxDynamicSharedMemorySize, K1_SMEM);
    cudaFuncSetAttribute(k2_pipe, cudaFuncAttributeMaxDynamicSharedMemorySize, K2_SMEM);

    kd_detect<<<1, 32>>>((const int*)E, 2 * n_edges);
    k0_prepw<<<512, 256>>>(W1);
    int tiles = (n_nodes + TILE_M - 1) / TILE_M;
    k1_gemm<<<tiles, 256, K1_SMEM>>>(X, n_nodes);

    const int G = 152;                         // one CTA per SM (GB300: 152 SMs)
    int epc = (n_edges + G - 1) / G;
    epc = ((epc + 31) / 32) * 32;              // multiple of stage size
    k2_pipe<<<G, 512, K2_SMEM>>>(E, b1, W2, b2, (float*)d_out, n_edges, n_nodes, epc);
}

// round 14
// speedup vs baseline: 1.5124x; 1.5124x over previous
#include <cuda_runtime.h>
#include <cuda_fp16.h>
#include <stdint.h>

// ============================================================================
// LinkPrediction on GB300 (sm_103 base target: mma.sync + ldmatrix; tcgen05
// unusable — harness PTX targets sm_103 without 'a').
//
//   out[e] = relu( relu(x[src])@W1top + relu(x[dst])@W1bot + b1 ) @ W2 + b2
//
//   K0: pre-swizzle Wcat^T fp16 image.     Kd: edge dtype oracle.
//   K1: AB = relu(X)@Wcat via HMMA (at legacy-HMMA roofline; split into
//       ABs = cols 0:512 (src half) and ABd = cols 512:1024 (dst half)).
//   Sort: bucket edges by src>>4 (histogram + scan + scatter of (src,dst,e))
//       -> src gathers near-sequential w/ L1 reuse; dst random footprint
//       (102MB) now fits L2. Cuts K2 DRAM traffic ~2x.
//   K2: R12-proven register pipeline (2 edges/warp-iter, 8 in-flight gathers),
//       fed by sorted edata, scattered float2 output.
// ============================================================================

#define TILE_M   128
#define HID      128
#define NBUCK    6250        // 100000/16 node buckets

__device__ __align__(16) __half g_Wsw[1024 * 128];            // swizzled Wcat^T
__device__ __align__(16) __half g_ABs[(size_t)100096 * 512];  // src halves (~102MB)
__device__ __align__(16) __half g_ABd[(size_t)100096 * 512];  // dst halves (~102MB)
__device__ int  g_e64;
__device__ int  g_hist[NBUCK];
__device__ int  g_cursor[NBUCK];
__device__ __align__(16) int4 g_edata[500032];                // (src,dst,e,0) sorted

__device__ __forceinline__ uint32_t smem_u32(const void* p) {
    uint32_t a;
    asm("{ .reg .u64 t; cvta.to.shared.u64 t, %1; cvt.u32.u64 %0, t; }" : "=r"(a) : "l"(p));
    return a;
}
__device__ __host__ __forceinline__ uint32_t swiz16(uint32_t row, uint32_t c) {
    return ((c & ~7u) | ((c ^ row) & 7u)) << 4;
}
__device__ __forceinline__ void ldm_x4(uint32_t* r, uint32_t addr) {
    asm volatile("ldmatrix.sync.aligned.m8n8.x4.shared.b16 {%0,%1,%2,%3}, [%4];"
                 : "=r"(r[0]), "=r"(r[1]), "=r"(r[2]), "=r"(r[3]) : "r"(addr));
}
__device__ __forceinline__ void mma16816(float* d, const uint32_t* a,
                                         uint32_t b0, uint32_t b1) {
    asm volatile(
        "mma.sync.aligned.m16n8k16.row.col.f32.f16.f16.f32 "
        "{%0,%1,%2,%3}, {%4,%5,%6,%7}, {%8,%9}, {%0,%1,%2,%3};"
        : "+f"(d[0]), "+f"(d[1]), "+f"(d[2]), "+f"(d[3])
        : "r"(a[0]), "r"(a[1]), "r"(a[2]), "r"(a[3]), "r"(b0), "r"(b1));
}
__device__ __forceinline__ void cp_async16(uint32_t dst, const void* src) {
    asm volatile("cp.async.cg.shared.global [%0], [%1], 16;" :: "r"(dst), "l"(src));
}

// ============================================================================
// Kd: edge-dtype oracle. int64 edges (<100000) => every odd int32 word is 0.
// ============================================================================
__global__ void kd_detect(const int* __restrict__ E32, int n_words) {
    __shared__ int any_nz;
    if (threadIdx.x == 0) any_nz = 0;
    __syncthreads();
    int stride = (n_words / 2) / 256;
    if (stride < 1) stride = 1;
    int nz = 0;
    for (int i = threadIdx.x; i < 256; i += blockDim.x) {
        int idx = 2 * (i * stride) + 1;
        if (idx < n_words && E32[idx] != 0) nz = 1;
    }
    if (nz) atomicOr(&any_nz, 1);
    __syncthreads();
    if (threadIdx.x == 0) g_e64 = any_nz ? 0 : 1;
}

// ============================================================================
// Edge sort: zero -> histogram -> scan -> scatter (src,dst,e) into buckets.
// ============================================================================
__global__ void kz_zero() {
    int i = blockIdx.x * blockDim.x + threadIdx.x;
    if (i < NBUCK) g_hist[i] = 0;
}

__device__ __forceinline__ int edge_src(const void* Ev, int e, int n_edges, int e64) {
    return e64 ? (int)__ldg((const long long*)Ev + e) : __ldg((const int*)Ev + e);
}
__device__ __forceinline__ int edge_dst(const void* Ev, int e, int n_edges, int e64) {
    return e64 ? (int)__ldg((const long long*)Ev + (size_t)n_edges + e)
               : __ldg((const int*)Ev + (size_t)n_edges + e);
}

__global__ void kh_hist(const void* __restrict__ Ev, int n_edges, int n_nodes) {
    int e64 = g_e64;
    for (int e = blockIdx.x * blockDim.x + threadIdx.x; e < n_edges;
         e += gridDim.x * blockDim.x) {
        int s = edge_src(Ev, e, n_edges, e64);
        s = min(max(s, 0), n_nodes - 1);
        atomicAdd(&g_hist[s >> 4], 1);
    }
}

__global__ void ks_scan() {   // 1 CTA, 1024 threads; exclusive scan -> g_cursor
    __shared__ int tsum[1024];
    int t = threadIdx.x;
    const int CH = (NBUCK + 1023) / 1024;   // 7
    int local[CH];
    int s = 0;
#pragma unroll
    for (int j = 0; j < CH; j++) {
        int idx = t * CH + j;
        int v = (idx < NBUCK) ? g_hist[idx] : 0;
        local[j] = s; s += v;
    }
    tsum[t] = s;
    __syncthreads();
    for (int off = 1; off < 1024; off <<= 1) {
        int v = (t >= off) ? tsum[t - off] : 0;
        __syncthreads();
        tsum[t] += v;
        __syncthreads();
    }
    int pre = (t > 0) ? tsum[t - 1] : 0;
#pragma unroll
    for (int j = 0; j < CH; j++) {
        int idx = t * CH + j;
        if (idx < NBUCK) g_cursor[idx] = pre + local[j];
    }
}

__global__ void kp_scatter(const void* __restrict__ Ev, int n_edges, int n_nodes) {
    int e64 = g_e64;
    for (int e = blockIdx.x * blockDim.x + threadIdx.x; e < n_edges;
         e += gridDim.x * blockDim.x) {
        int s = edge_src(Ev, e, n_edges, e64);
        int d = edge_dst(Ev, e, n_edges, e64);
        int sc = min(max(s, 0), n_nodes - 1);
        int pos = atomicAdd(&g_cursor[sc >> 4], 1);
        g_edata[pos] = make_int4(sc, min(max(d, 0), n_nodes - 1), e, 0);
    }
}

// ============================================================================
// K0: g_Wsw[n][k] = Wcat[k][n] (fp16), swizzled.
// ============================================================================
__global__ void k0_prepw(const float* __restrict__ W1) {
    int idx = blockIdx.x * blockDim.x + threadIdx.x;
    if (idx >= 1024 * 128) return;
    int n = idx >> 7;
    int k = idx & 127;
    float val = (n < 512) ? W1[k * 512 + n] : W1[(k + 128) * 512 + (n - 512)];
    uint32_t c = (uint32_t)(k >> 3), i = (uint32_t)(k & 7);
    g_Wsw[(size_t)n * 128 + (swiz16((uint32_t)n, c) >> 1) + i] = __float2half(val);
}

// ============================================================================
// K1: 256 thr = 8 warps (4M x 2N), warp tile 32x64, 8 N-chunks of 128.
// cp.async double-buffered B; staged coalesced fp16 writeback split ABs/ABd.
// ============================================================================
__global__ void __launch_bounds__(256, 2) k1_gemm(const float* __restrict__ X, int n_nodes) {
    extern __shared__ char smem[];
    uint32_t smemA = smem_u32(smem);
    uint32_t smemB[2] = { smemA + 32768u, smemA + 65536u };

    int tid = threadIdx.x, wid = tid >> 5, lid = tid & 31;
    int warp_m = wid & 3;
    int warp_n = wid >> 2;

    {
        const int4* src = (const int4*)(g_Wsw);
#pragma unroll
        for (int i = tid; i < 2048; i += 256) cp_async16(smemB[0] + i * 16, src + i);
        asm volatile("cp.async.commit_group;");
    }

    {
        int row = tid >> 1;
        int kbase = (tid & 1) * 64;
        int node = blockIdx.x * TILE_M + row;
        bool v = (node < n_nodes);
        const float4* xr = (const float4*)(X + (size_t)(v ? node : 0) * HID + kbase);
#pragma unroll
        for (int j = 0; j < 16; j++) {
            float4 val = v ? __ldg(xr + j) : make_float4(0.f, 0.f, 0.f, 0.f);
            val.x = fmaxf(val.x, 0.f); val.y = fmaxf(val.y, 0.f);
            val.z = fmaxf(val.z, 0.f); val.w = fmaxf(val.w, 0.f);
            union { __half2 h; uint32_t u; } p0, p1;
            p0.h = __floats2half2_rn(val.x, val.y);
            p1.h = __floats2half2_rn(val.z, val.w);
            int col = kbase + j * 4;
            uint32_t c = (uint32_t)(col >> 3), i = (uint32_t)(col & 7);
            uint32_t dst = smemA + (uint32_t)row * 256u + swiz16((uint32_t)row, c) + i * 2u;
            asm volatile("st.shared.v2.b32 [%0], {%1, %2};" :: "r"(dst), "r"(p0.u), "r"(p1.u));
        }
    }

    size_t ctabase = (size_t)blockIdx.x * TILE_M;

    uint32_t rowA_base = (uint32_t)(warp_m * 32) + (uint32_t)(lid & 15);
    uint32_t cA_lane = (uint32_t)(lid >> 4);
    uint32_t rowB_base = (uint32_t)(warp_n * 64) + (uint32_t)(((lid >> 4) << 3) + (lid & 7));
    uint32_t cB_lane = (uint32_t)((lid >> 3) & 1);

    for (int chunk = 0; chunk < 8; chunk++) {
        int cur = chunk & 1;
        __syncthreads();
        if (chunk + 1 < 8) {
            const int4* src = (const int4*)(g_Wsw + (size_t)(chunk + 1) * 16384);
            uint32_t dstb = smemB[cur ^ 1];
#pragma unroll
            for (int i = tid; i < 2048; i += 256) cp_async16(dstb + i * 16, src + i);
            asm volatile("cp.async.commit_group;");
            asm volatile("cp.async.wait_group 1;");
        } else {
            asm volatile("cp.async.wait_group 0;");
        }
        __syncthreads();

        float acc[2][8][4];
#pragma unroll
        for (int mt = 0; mt < 2; mt++)
#pragma unroll
            for (int nt = 0; nt < 8; nt++)
#pragma unroll
                for (int q = 0; q < 4; q++) acc[mt][nt][q] = 0.f;

        uint32_t sB = smemB[cur];
#pragma unroll
        for (int ks = 0; ks < 8; ks++) {
            uint32_t a[2][4];
#pragma unroll
            for (int mt = 0; mt < 2; mt++) {
                uint32_t row = rowA_base + (uint32_t)(mt * 16);
                uint32_t c = (uint32_t)(ks * 2) + cA_lane;
                ldm_x4(a[mt], smemA + row * 256u + swiz16(row, c));
            }
#pragma unroll
            for (int ntp = 0; ntp < 4; ntp++) {
                uint32_t bb[4];
                uint32_t row = rowB_base + (uint32_t)(ntp * 16);
                uint32_t c = (uint32_t)(ks * 2) + cB_lane;
                ldm_x4(bb, sB + row * 256u + swiz16(row, c));
                mma16816(acc[0][2 * ntp],     a[0], bb[0], bb[1]);
                mma16816(acc[0][2 * ntp + 1], a[0], bb[2], bb[3]);
                mma16816(acc[1][2 * ntp],     a[1], bb[0], bb[1]);
                mma16816(acc[1][2 * ntp + 1], a[1], bb[2], bb[3]);
            }
        }
        __syncthreads();

        {
            uint32_t r0 = (uint32_t)(lid >> 2);
            uint32_t inner = (uint32_t)(lid & 3) * 4u;
#pragma unroll
            for (int mt = 0; mt < 2; mt++) {
#pragma unroll
                for (int nt = 0; nt < 8; nt++) {
                    uint32_t c16 = (uint32_t)(warp_n * 8 + nt);
                    uint32_t rowa = (uint32_t)(warp_m * 32 + mt * 16) + r0;
                    uint32_t rowb = rowa + 8;
                    union { __half2 h; uint32_t u; } h01, h23;
                    h01.h = __floats2half2_rn(acc[mt][nt][0], acc[mt][nt][1]);
                    h23.h = __floats2half2_rn(acc[mt][nt][2], acc[mt][nt][3]);
                    asm volatile("st.shared.b32 [%0], %1;"
                                 :: "r"(sB + rowa * 256u + swiz16(rowa, c16) + inner), "r"(h01.u));
                    asm volatile("st.shared.b32 [%0], %1;"
                                 :: "r"(sB + rowb * 256u + swiz16(rowb, c16) + inner), "r"(h23.u));
                }
            }
        }
        __syncthreads();

        {
            const char* stp = smem + 32768 + cur * 32768;
            __half* dsta = (chunk < 4) ? g_ABs : g_ABd;
            int colbase = (chunk & 3) * 128;
#pragma unroll
            for (int i = tid; i < 2048; i += 256) {
                uint32_t row = (uint32_t)(i >> 4), c16 = (uint32_t)(i & 15);
                int4 v = *(const int4*)(stp + row * 256u + swiz16(row, c16));
                *(int4*)(dsta + (ctabase + row) * 512 + colbase + c16 * 8) = v;
            }
        }
    }
}

// ============================================================================
// K2: sorted-edge gather. 2 edges per warp iteration; blocked pair ranges so
// consecutive iterations share src buckets (L1 reuse). 8 in-flight 16B gathers
// per lane; R12-proven epilogue (fp32 adds, packed fp16 consts, 79 regs).
// ============================================================================
union I4H { int4 v; __half2 h[8]; };

__device__ __forceinline__ void edge_partial(const I4H& a0, const I4H& a1,
                                             const I4H& v0, const I4H& v1,
                                             const __half2* b1p, const __half2* w2p,
                                             float& acc0, float& acc1) {
    acc0 = 0.f; acc1 = 0.f;
#pragma unroll
    for (int q = 0; q < 4; q++) {
        float2 fa = __half22float2(a0.h[q]);
        float2 fb = __half22float2(v0.h[q]);
        float2 bb = __half22float2(b1p[q]);
        float2 wA = __half22float2(w2p[2 * q]);
        float2 wB = __half22float2(w2p[2 * q + 1]);
        float h0 = fmaxf(fa.x + fb.x + bb.x, 0.f);
        float h1 = fmaxf(fa.y + fb.y + bb.y, 0.f);
        acc0 = fmaf(h0, wA.x, acc0); acc1 = fmaf(h0, wA.y, acc1);
        acc0 = fmaf(h1, wB.x, acc0); acc1 = fmaf(h1, wB.y, acc1);
    }
#pragma unroll
    for (int q = 0; q < 4; q++) {
        float2 fa = __half22float2(a1.h[q]);
        float2 fb = __half22float2(v1.h[q]);
        float2 bb = __half22float2(b1p[4 + q]);
        float2 wA = __half22float2(w2p[8 + 2 * q]);
        float2 wB = __half22float2(w2p[8 + 2 * q + 1]);
        float h0 = fmaxf(fa.x + fb.x + bb.x, 0.f);
        float h1 = fmaxf(fa.y + fb.y + bb.y, 0.f);
        acc0 = fmaf(h0, wA.x, acc0); acc1 = fmaf(h0, wA.y, acc1);
        acc0 = fmaf(h1, wB.x, acc0); acc1 = fmaf(h1, wB.y, acc1);
    }
}

__global__ void __launch_bounds__(256, 3) k2_edge(const float* __restrict__ b1,
                                                  const float* __restrict__ W2,
                                                  const float* __restrict__ b2,
                                                  float* __restrict__ out,
                                                  int n_edges) {
    int lid = threadIdx.x & 31;
    int gw = (blockIdx.x * blockDim.x + threadIdx.x) >> 5;
    int nw = (gridDim.x * blockDim.x) >> 5;
    int cb = lid * 16;

    __half2 b1p[8], w2p[16];
#pragma unroll
    for (int j = 0; j < 8; j++)
        b1p[j] = __floats2half2_rn(__ldg(b1 + cb + 2 * j), __ldg(b1 + cb + 2 * j + 1));
#pragma unroll
    for (int j = 0; j < 16; j++)
        w2p[j] = __floats2half2_rn(__ldg(W2 + (cb + j) * 2), __ldg(W2 + (cb + j) * 2 + 1));
    float b20 = __ldg(b2), b21 = __ldg(b2 + 1);

    int npairs = (n_edges + 1) >> 1;
    int len = (npairs + nw - 1) / nw;
    int p = gw * len;
    int pend = min(p + len, npairs);
    if (p >= pend) return;

    int4 ed0 = __ldg(&g_edata[2 * p]);
    int4 ed1 = (2 * p + 1 < n_edges) ? __ldg(&g_edata[2 * p + 1])
                                     : make_int4(0, 0, -1, 0);

    while (true) {
        // 8 independent gathers issued before any consumption
        const int4* pa0 = (const int4*)(g_ABs + (size_t)ed0.x * 512 + cb);
        const int4* pb0 = (const int4*)(g_ABd + (size_t)ed0.y * 512 + cb);
        const int4* pa1 = (const int4*)(g_ABs + (size_t)ed1.x * 512 + cb);
        const int4* pb1 = (const int4*)(g_ABd + (size_t)ed1.y * 512 + cb);
        I4H a00, a01, v00, v01, a10, a11, v10, v11;
        a00.v = __ldg(pa0);  a01.v = __ldg(pa0 + 1);
        v00.v = __ldg(pb0);  v01.v = __ldg(pb0 + 1);
        a10.v = __ldg(pa1);  a11.v = __ldg(pa1 + 1);
        v10.v = __ldg(pb1);  v11.v = __ldg(pb1 + 1);

        // prefetch next pair's edge records (sequential, broadcast)
        int pn = p + 1;
        bool more = (pn < pend);
        int4 ned0 = make_int4(0, 0, -1, 0), ned1 = make_int4(0, 0, -1, 0);
        if (more) {
            ned0 = __ldg(&g_edata[2 * pn]);
            if (2 * pn + 1 < n_edges) ned1 = __ldg(&g_edata[2 * pn + 1]);
        }

        float x0, x1, y0, y1;
        edge_partial(a00, a01, v00, v01, b1p, w2p, x0, x1);
        edge_partial(a10, a11, v10, v11, b1p, w2p, y0, y1);

#pragma unroll
        for (int s = 16; s >= 1; s >>= 1) {
            x0 += __shfl_xor_sync(0xffffffffu, x0, s);
            x1 += __shfl_xor_sync(0xffffffffu, x1, s);
            y0 += __shfl_xor_sync(0xffffffffu, y0, s);
            y1 += __shfl_xor_sync(0xffffffffu, y1, s);
        }
        if (lid == 0) {
            *(float2*)(out + 2 * (size_t)ed0.z) = make_float2(x0 + b20, x1 + b21);
            if (ed1.z >= 0)
                *(float2*)(out + 2 * (size_t)ed1.z) = make_float2(y0 + b20, y1 + b21);
        }

        if (!more) break;
        p = pn; ed0 = ned0; ed1 = ned1;
    }
}

// ============================================================================
extern "C" void kernel_launch(void* const* d_in, const int* in_sizes, int n_in,
                              void* d_out, int out_size) {
    const float* X = nullptr; const void* E = nullptr;
    const float *W1 = nullptr, *b1 = nullptr, *W2 = nullptr, *b2 = nullptr;
    int n_nodes = 0, n_edges = 0;
    for (int i = 0; i < n_in; i++) {
        switch (in_sizes[i]) {
            case 12800000: X  = (const float*)d_in[i]; n_nodes = in_sizes[i] / 128; break;
            case 1000000:  E  = d_in[i];               n_edges = in_sizes[i] / 2;   break;
            case 131072:   W1 = (const float*)d_in[i]; break;
            case 512:      b1 = (const float*)d_in[i]; break;
            case 1024:     W2 = (const float*)d_in[i]; break;
            case 2:        b2 = (const float*)d_in[i]; break;
        }
    }
    if (!X || !E || !W1 || !b1 || !W2 || !b2) return;

    const int K1_SMEM = 98304;   // A 32KB + B0 32KB + B1 32KB
    cudaFuncSetAttribute(k1_gemm, cudaFuncAttributeMaxDynamicSharedMemorySize, K1_SMEM);

    kd_detect<<<1, 32>>>((const int*)E, 2 * n_edges);
    kz_zero<<<(NBUCK + 511) / 512, 512>>>();
    kh_hist<<<488, 512>>>(E, n_edges, n_nodes);
    ks_scan<<<1, 1024>>>();
    kp_scatter<<<488, 512>>>(E, n_edges, n_nodes);

    k0_prepw<<<512, 256>>>(W1);
    int tiles = (n_nodes + TILE_M - 1) / TILE_M;
    k1_gemm<<<tiles, 256, K1_SMEM>>>(X, n_nodes);
    k2_edge<<<888, 256>>>(b1, W2, b2, (float*)d_out, n_edges);
}